// round 12
// baseline (speedup 1.0000x reference)
#include <cuda_runtime.h>
#include <cstdint>

#define NM    100
#define NPAD  101          // padded bins per lane (odd stride -> conflict-free LDS.64)
#define WARPS 8
#define BLK   (WARPS*32)
#define TP    16
#define KCH   91           // 13 wr * 91 = 1183 tasks = 148*8-1 warps
#define WR    13
#define NTASK (WR*KCH)
#define NSEG  7
#define KSEG  13
#define HBLK  148

#define ACC_BYTES (BLK*NPAD*sizeof(float2))   /* 206848 B -> 1 block/SM, 8 warps */

__device__ float2   g_acc[(size_t)NTASK * NM * 32];   // ~30.3 MB
__device__ float2   g_sc [(size_t)NTASK * 32];        // (SumU, SumV) per task-lane
__device__ int      g_hist[HBLK * NM];
__device__ int      g_counts[NM];
__device__ uint32_t g_labpack[65536];
__device__ float2   g_part [(size_t)NSEG * NM * WR * 32];
__device__ float2   g_spart[(size_t)NSEG * WR * 32];
__device__ float2   g_rowsum[WR * 32];                // (Sum_d, Sum_s) per query

// ---------- packed f32x2 helpers ----------
__device__ __forceinline__ uint64_t pk(float lo, float hi) {
    uint64_t r; asm("mov.b64 %0, {%1,%2};" : "=l"(r) : "f"(lo), "f"(hi)); return r;
}
__device__ __forceinline__ void upk(uint64_t v, float& lo, float& hi) {
    asm("mov.b64 {%0,%1}, %2;" : "=f"(lo), "=f"(hi) : "l"(v));
}
__device__ __forceinline__ uint64_t f2add(uint64_t a, uint64_t b) {
    uint64_t d; asm("add.rn.f32x2 %0, %1, %2;" : "=l"(d) : "l"(a), "l"(b)); return d;
}
__device__ __forceinline__ uint64_t f2mul(uint64_t a, uint64_t b) {
    uint64_t d; asm("mul.rn.f32x2 %0, %1, %2;" : "=l"(d) : "l"(a), "l"(b)); return d;
}
__device__ __forceinline__ uint64_t f2fma(uint64_t a, uint64_t b, uint64_t c) {
    uint64_t d; asm("fma.rn.f32x2 %0, %1, %2, %3;" : "=l"(d) : "l"(a), "l"(b), "l"(c)); return d;
}

__global__ void pack_labels_kernel(const int* __restrict__ labels, int P) {
    const int i = blockIdx.x * blockDim.x + threadIdx.x;
    const int base = i * 4;
    if (base >= P) return;
    uint32_t w = 0;
    if (base + 3 < P) {
        int4 l = *reinterpret_cast<const int4*>(labels + base);
        w = (uint32_t)(l.x & 0xFF) | ((uint32_t)(l.y & 0xFF) << 8) |
            ((uint32_t)(l.z & 0xFF) << 16) | ((uint32_t)(l.w & 0xFF) << 24);
    } else {
        for (int k = 0; k < 4 && base + k < P; ++k)
            w |= (uint32_t)(labels[base + k] & 0xFF) << (8 * k);
    }
    g_labpack[i] = w;
}

__global__ void hist_kernel(const int* __restrict__ labels, int P) {
    __shared__ int sb[NM];
    for (int i = threadIdx.x; i < NM; i += blockDim.x) sb[i] = 0;
    __syncthreads();
    for (int i = blockIdx.x * blockDim.x + threadIdx.x; i < P;
         i += gridDim.x * blockDim.x) {
        int l = labels[i];
        if ((unsigned)l < (unsigned)NM) atomicAdd(&sb[l], 1);
    }
    __syncthreads();
    for (int i = threadIdx.x; i < NM; i += blockDim.x)
        g_hist[blockIdx.x * NM + i] = sb[i];
}

// scalar fallback for tail points (uses MUFU log; rarely executed)
__device__ __forceinline__ void point_math_scalar(float x, float& d, float& U,
                                                  float& V, float& s) {
    const float ax = fabsf(x);
    const float t  = __expf(-ax);
    const float dn = 1.0f + t;
    const float r  = __fdividef(1.0f, dn);
    const float tr = t * r;
    const float L  = __logf(dn);
    const float Lm = L + ax;
    U = (tr * tr) * L;
    V = (r * r) * Lm;
    const bool pos = (x >= 0.0f);
    s = pos ? r : tr;
    d = pos ? fmaf(-3.0f, V, U) : fmaf(-3.0f, U, V);
}

__global__ __launch_bounds__(BLK, 1)
void main_kernel(const float* __restrict__ pred, const int* __restrict__ labels,
                 int Q, int P, int pc) {
    extern __shared__ float2 acc[];

    const int tid  = threadIdx.x;
    const int w    = tid >> 5;
    const int lane = tid & 31;

    float2* myacc = acc + tid * NPAD;
    #pragma unroll 4
    for (int j = 0; j < NPAD; ++j) myacc[j] = make_float2(0.f, 0.f);

    const int g = w * gridDim.x + blockIdx.x;
    if (g >= NTASK) return;
    const int wr = g / KCH;
    const int k  = g - wr * KCH;

    const int q  = wr * 32 + lane;
    const int qc = (q < Q) ? q : (Q - 1);
    const float* __restrict__ rowp = pred + (size_t)qc * P;

    const int pstart = k * pc;
    const int pend   = (pstart + pc < P) ? (pstart + pc) : P;

    // packed constants (loop-invariant)
    const uint64_t ONE = pk(1.0f, 1.0f);
    const uint64_t MONE= pk(-1.0f, -1.0f);
    const uint64_t TWO = pk(2.0f, 2.0f);
    const uint64_t CA  = pk(-0.470588235f, -0.470588235f);  // -8/17
    const uint64_t CB  = pk(1.411764706f, 1.411764706f);    // 24/17
    const uint64_t M3  = pk(-3.0f, -3.0f);
    const uint64_t A1  = pk(0.9999964239f, 0.9999964239f);
    const uint64_t A2  = pk(-0.4998741238f, -0.4998741238f);
    const uint64_t A3  = pk(0.3317990258f, 0.3317990258f);
    const uint64_t A4  = pk(-0.2407338084f, -0.2407338084f);
    const uint64_t A5  = pk(0.1676540711f, 0.1676540711f);
    const uint64_t A6  = pk(-0.0953293897f, -0.0953293897f);
    const uint64_t A7  = pk(0.0360884937f, 0.0360884937f);
    const uint64_t A8  = pk(-0.0064535442f, -0.0064535442f);

    uint64_t sumU2 = pk(0.f, 0.f);
    uint64_t sumV2 = pk(0.f, 0.f);

    const uint32_t accaddr = (uint32_t)__cvta_generic_to_shared(myacc);

    if (pstart < pend) {
        const int npts  = pend - pstart;
        const int nfull = npts >> 4;
        const int ntail = npts & 15;

        float4 b0, b1, b2, b3;
        uint4  lw;
        {
            const float* rp = rowp + pstart;
            b0 = *reinterpret_cast<const float4*>(rp + 0);
            b1 = *reinterpret_cast<const float4*>(rp + 4);
            b2 = *reinterpret_cast<const float4*>(rp + 8);
            b3 = *reinterpret_cast<const float4*>(rp + 12);
            lw = *reinterpret_cast<const uint4*>(g_labpack + (pstart >> 2));
        }

        int pt0 = pstart;
        for (int tile = 0; tile < nfull; ++tile, pt0 += TP) {
            float c[TP];
            c[0]=b0.x; c[1]=b0.y; c[2]=b0.z; c[3]=b0.w;
            c[4]=b1.x; c[5]=b1.y; c[6]=b1.z; c[7]=b1.w;
            c[8]=b2.x; c[9]=b2.y; c[10]=b2.z; c[11]=b2.w;
            c[12]=b3.x; c[13]=b3.y; c[14]=b3.z; c[15]=b3.w;
            uint32_t lv[4] = {lw.x, lw.y, lw.z, lw.w};

            const int nxt = pt0 + TP;
            if (nxt + TP <= pend) {
                const float* rp = rowp + nxt;
                b0 = *reinterpret_cast<const float4*>(rp + 0);
                b1 = *reinterpret_cast<const float4*>(rp + 4);
                b2 = *reinterpret_cast<const float4*>(rp + 8);
                b3 = *reinterpret_cast<const float4*>(rp + 12);
                lw = *reinterpret_cast<const uint4*>(g_labpack + (nxt >> 2));
            }

            #pragma unroll
            for (int i = 0; i < TP / 2; ++i) {
                const float x0 = c[2*i], x1 = c[2*i+1];
                const float ax0 = fabsf(x0), ax1 = fabsf(x1);
                const float t0 = __expf(-ax0);
                const float t1 = __expf(-ax1);

                const uint64_t t  = pk(t0, t1);
                const uint64_t m  = pk(ax0, ax1);
                const uint64_t dn = f2add(t, ONE);
                const uint64_t ndn= f2mul(dn, MONE);
                uint64_t r = f2fma(dn, CA, CB);          // Newton recip
                r = f2mul(r, f2fma(ndn, r, TWO));
                r = f2mul(r, f2fma(ndn, r, TWO));
                const uint64_t tr = f2mul(t, r);
                uint64_t pl = f2fma(t, A8, A7);          // Hastings log(1+t)
                pl = f2fma(t, pl, A6);
                pl = f2fma(t, pl, A5);
                pl = f2fma(t, pl, A4);
                pl = f2fma(t, pl, A3);
                pl = f2fma(t, pl, A2);
                pl = f2fma(t, pl, A1);
                const uint64_t L  = f2mul(pl, t);
                const uint64_t Lm = f2add(L, m);
                const uint64_t U  = f2mul(f2mul(tr, tr), L);
                const uint64_t V  = f2mul(f2mul(r, r), Lm);
                const uint64_t dU = f2fma(V, M3, U);     // U - 3V  (x>=0)
                const uint64_t dV = f2fma(U, M3, V);     // V - 3U  (x<0)

                sumU2 = f2add(sumU2, U);
                sumV2 = f2add(sumV2, V);

                float r_0, r_1, tr_0, tr_1, dU_0, dU_1, dV_0, dV_1;
                upk(r, r_0, r_1); upk(tr, tr_0, tr_1);
                upk(dU, dU_0, dU_1); upk(dV, dV_0, dV_1);

                {   // point 2i
                    const int lab = (int)__byte_perm(lv[i >> 1], 0,
                                                     0x4440u + ((2*i) & 3));
                    const bool pos = (x0 >= 0.0f);
                    const uint64_t ds = pk(pos ? dU_0 : dV_0, pos ? r_0 : tr_0);
                    const uint32_t ad = accaddr + (uint32_t)lab * 8u;
                    uint64_t a;
                    asm("ld.shared.b64 %0, [%1];" : "=l"(a) : "r"(ad));
                    a = f2add(a, ds);
                    asm("st.shared.b64 [%0], %1;" :: "r"(ad), "l"(a));
                }
                {   // point 2i+1
                    const int lab = (int)__byte_perm(lv[i >> 1], 0,
                                                     0x4440u + ((2*i+1) & 3));
                    const bool pos = (x1 >= 0.0f);
                    const uint64_t ds = pk(pos ? dU_1 : dV_1, pos ? r_1 : tr_1);
                    const uint32_t ad = accaddr + (uint32_t)lab * 8u;
                    uint64_t a;
                    asm("ld.shared.b64 %0, [%1];" : "=l"(a) : "r"(ad));
                    a = f2add(a, ds);
                    asm("st.shared.b64 [%0], %1;" :: "r"(ad), "l"(a));
                }
            }
        }

        if (ntail) {
            #pragma unroll
            for (int i = 0; i < TP; ++i) {
                if (i < ntail) {
                    const int lab = labels[pt0 + i];
                    float d, U, V, s;
                    point_math_scalar(rowp[pt0 + i], d, U, V, s);
                    float2 a = myacc[lab];
                    a.x += d; a.y += s;
                    myacc[lab] = a;
                    sumU2 = f2add(sumU2, pk(U, 0.f));
                    sumV2 = f2add(sumV2, pk(V, 0.f));
                }
            }
        }
    }

    float2* dst = g_acc + (size_t)g * NM * 32;
    #pragma unroll 4
    for (int j = 0; j < NM; ++j) dst[j * 32 + lane] = myacc[j];
    float su0, su1, sv0, sv1;
    upk(sumU2, su0, su1); upk(sumV2, sv0, sv1);
    g_sc[(size_t)g * 32 + lane] = make_float2(su0 + su1, sv0 + sv1);
}

// stage 1: grid (NM/8, WR, NSEG), block (32,8)
__global__ void reduce1_kernel() {
    const int lane = threadIdx.x;
    const int ty   = threadIdx.y;
    const int j    = blockIdx.x * 8 + ty;
    const int wr   = blockIdx.y;
    const int seg  = blockIdx.z;

    if (j < NM) {
        float s1 = 0.f, s2 = 0.f;
        const size_t base = (size_t)wr * KCH + seg * KSEG;
        #pragma unroll
        for (int k = 0; k < KSEG; ++k) {
            float2 a = g_acc[((base + k) * NM + j) * 32 + lane];
            s1 += a.x; s2 += a.y;
        }
        g_part[(((size_t)seg * NM + j) * WR + wr) * 32 + lane] = make_float2(s1, s2);
    }

    if (ty == 0 && blockIdx.x == 0) {
        float su = 0.f, sv = 0.f;
        const size_t base = (size_t)wr * KCH + seg * KSEG;
        #pragma unroll
        for (int k = 0; k < KSEG; ++k) {
            float2 s = g_sc[(base + k) * 32 + lane];
            su += s.x; sv += s.y;
        }
        g_spart[((size_t)seg * WR + wr) * 32 + lane] = make_float2(su, sv);
    }

    if (seg == 0 && wr == 0 && j < NM) {
        int c = 0;
        for (int b = lane; b < HBLK; b += 32) c += g_hist[b * NM + j];
        #pragma unroll
        for (int o = 16; o > 0; o >>= 1) c += __shfl_xor_sync(0xffffffffu, c, o);
        if (lane == 0) g_counts[j] = c;
    }
}

// per-query totals: Sd = sum_j bins.x, Sp = sum_j bins.y
__global__ void rowsum_kernel() {
    __shared__ float2 sb[8][33];
    const int lane = threadIdx.x;
    const int ty   = threadIdx.y;
    const int wr   = blockIdx.x;
    float sd = 0.f, sp = 0.f;
    for (int mm = 0; mm < 13; ++mm) {
        const int j = ty + 8 * mm;
        if (j < NM) {
            #pragma unroll
            for (int seg = 0; seg < NSEG; ++seg) {
                float2 a = g_part[(((size_t)seg * NM + j) * WR + wr) * 32 + lane];
                sd += a.x; sp += a.y;
            }
        }
    }
    sb[ty][lane] = make_float2(sd, sp);
    __syncthreads();
    if (ty == 0) {
        float2 tt = sb[0][lane];
        #pragma unroll
        for (int y = 1; y < 8; ++y) { tt.x += sb[y][lane].x; tt.y += sb[y][lane].y; }
        g_rowsum[wr * 32 + lane] = tt;
    }
}

// stage 2: grid (NM/8, WR), block (32,8)
__global__ void reduce2_kernel(float* __restrict__ out, int Q, float invP) {
    const int lane = threadIdx.x;
    const int j    = blockIdx.x * 8 + threadIdx.y;
    const int wr   = blockIdx.y;
    const int q    = wr * 32 + lane;
    if (q >= Q || j >= NM) return;

    float s1 = 0.f, s2 = 0.f, su = 0.f, sv = 0.f;
    #pragma unroll
    for (int seg = 0; seg < NSEG; ++seg) {
        float2 a = g_part[(((size_t)seg * NM + j) * WR + wr) * 32 + lane];
        float2 s = g_spart[((size_t)seg * WR + wr) * 32 + lane];
        s1 += a.x; s2 += a.y;
        su += s.x; sv += s.y;
    }
    const float2 rs = g_rowsum[wr * 32 + lane];   // (Sd, Sp)
    const float sumB = (su + sv - rs.x) * 0.25f;  // {A,B}={U,V}: B=(U+V-d)/4
    const float cnt = (float)g_counts[j];
    const float cost_mask = (0.25f * s1 + 0.75f * sumB) * invP;
    const float cost_dice = 1.0f - (2.0f * s2 + 1.0f) / (rs.y + cnt + 1.0f);
    out[(size_t)q * NM + j] = cost_mask + cost_dice;
}

extern "C" void kernel_launch(void* const* d_in, const int* in_sizes, int n_in,
                              void* d_out, int out_size) {
    const float* pred   = (const float*)d_in[0];
    const int*   labels = (const int*)d_in[1];

    const int P = in_sizes[1];
    const int Q = in_sizes[0] / P;
    const int pc = (((P + KCH - 1) / KCH) + TP - 1) / TP * TP;

    cudaFuncSetAttribute(main_kernel, cudaFuncAttributeMaxDynamicSharedMemorySize,
                         ACC_BYTES);

    pack_labels_kernel<<<(P / 4 + 256) / 256 + 1, 256>>>(labels, P);
    hist_kernel<<<HBLK, 256>>>(labels, P);
    main_kernel<<<148, BLK, ACC_BYTES>>>(pred, labels, Q, P, pc);
    reduce1_kernel<<<dim3((NM + 7) / 8, WR, NSEG), dim3(32, 8)>>>();
    rowsum_kernel<<<WR, dim3(32, 8)>>>();
    reduce2_kernel<<<dim3((NM + 7) / 8, WR), dim3(32, 8)>>>((float*)d_out, Q,
                                                            1.0f / (float)P);
}

// round 13
// speedup vs baseline: 1.0045x; 1.0045x over previous
#include <cuda_runtime.h>
#include <cstdint>

#define NM    100
#define NPAD  101          // padded bins per lane (odd stride -> conflict-free LDS.64)
#define WARPS 8
#define BLK   (WARPS*32)
#define TP    16
#define KCH   91           // 13 wr * 91 = 1183 tasks = 148*8-1 warps
#define WR    13
#define NTASK (WR*KCH)
#define NSEG  7
#define KSEG  13
#define HBLK  148

#define ACC_BYTES (BLK*NPAD*sizeof(float2))   /* 206848 B -> 1 block/SM, 8 warps */

__device__ float2   g_acc[(size_t)NTASK * NM * 32];   // ~30.3 MB
__device__ float2   g_sc [(size_t)NTASK * 32];        // (SumU, SumV) per task-lane
__device__ int      g_hist[HBLK * NM];
__device__ int      g_counts[NM];
__device__ uint32_t g_labpack[65536];
__device__ float2   g_part [(size_t)NSEG * NM * WR * 32];
__device__ float2   g_spart[(size_t)NSEG * WR * 32];
__device__ float2   g_rowsum[WR * 32];                // (Sum_d, Sum_s) per query

// ---------- packed f32x2 helpers ----------
__device__ __forceinline__ uint64_t pk(float lo, float hi) {
    uint64_t r; asm("mov.b64 %0, {%1,%2};" : "=l"(r) : "f"(lo), "f"(hi)); return r;
}
__device__ __forceinline__ void upk(uint64_t v, float& lo, float& hi) {
    asm("mov.b64 {%0,%1}, %2;" : "=f"(lo), "=f"(hi) : "l"(v));
}
__device__ __forceinline__ uint64_t f2add(uint64_t a, uint64_t b) {
    uint64_t d; asm("add.rn.f32x2 %0, %1, %2;" : "=l"(d) : "l"(a), "l"(b)); return d;
}
__device__ __forceinline__ uint64_t f2mul(uint64_t a, uint64_t b) {
    uint64_t d; asm("mul.rn.f32x2 %0, %1, %2;" : "=l"(d) : "l"(a), "l"(b)); return d;
}
__device__ __forceinline__ uint64_t f2fma(uint64_t a, uint64_t b, uint64_t c) {
    uint64_t d; asm("fma.rn.f32x2 %0, %1, %2, %3;" : "=l"(d) : "l"(a), "l"(b), "l"(c)); return d;
}

__global__ void pack_labels_kernel(const int* __restrict__ labels, int P) {
    const int i = blockIdx.x * blockDim.x + threadIdx.x;
    const int base = i * 4;
    if (base >= P) return;
    uint32_t w = 0;
    if (base + 3 < P) {
        int4 l = *reinterpret_cast<const int4*>(labels + base);
        w = (uint32_t)(l.x & 0xFF) | ((uint32_t)(l.y & 0xFF) << 8) |
            ((uint32_t)(l.z & 0xFF) << 16) | ((uint32_t)(l.w & 0xFF) << 24);
    } else {
        for (int k = 0; k < 4 && base + k < P; ++k)
            w |= (uint32_t)(labels[base + k] & 0xFF) << (8 * k);
    }
    g_labpack[i] = w;
}

__global__ void hist_kernel(const int* __restrict__ labels, int P) {
    __shared__ int sb[NM];
    for (int i = threadIdx.x; i < NM; i += blockDim.x) sb[i] = 0;
    __syncthreads();
    for (int i = blockIdx.x * blockDim.x + threadIdx.x; i < P;
         i += gridDim.x * blockDim.x) {
        int l = labels[i];
        if ((unsigned)l < (unsigned)NM) atomicAdd(&sb[l], 1);
    }
    __syncthreads();
    for (int i = threadIdx.x; i < NM; i += blockDim.x)
        g_hist[blockIdx.x * NM + i] = sb[i];
}

// scalar fallback for tail points (uses MUFU log; rarely executed)
__device__ __forceinline__ void point_math_scalar(float x, float& d, float& U,
                                                  float& V, float& s) {
    const float ax = fabsf(x);
    const float t  = __expf(-ax);
    const float dn = 1.0f + t;
    const float r  = __fdividef(1.0f, dn);
    const float tr = t * r;
    const float L  = __logf(dn);
    const float Lm = L + ax;
    U = (tr * tr) * L;
    V = (r * r) * Lm;
    const bool pos = (x >= 0.0f);
    s = pos ? r : tr;
    d = pos ? fmaf(-3.0f, V, U) : fmaf(-3.0f, U, V);
}

__global__ __launch_bounds__(BLK, 1)
void main_kernel(const float* __restrict__ pred, const int* __restrict__ labels,
                 int Q, int P, int pc) {
    extern __shared__ float2 acc[];

    const int tid  = threadIdx.x;
    const int w    = tid >> 5;
    const int lane = tid & 31;

    float2* myacc = acc + tid * NPAD;
    #pragma unroll 4
    for (int j = 0; j < NPAD; ++j) myacc[j] = make_float2(0.f, 0.f);

    const int g = w * gridDim.x + blockIdx.x;
    if (g >= NTASK) return;
    const int wr = g / KCH;
    const int k  = g - wr * KCH;

    const int q  = wr * 32 + lane;
    const int qc = (q < Q) ? q : (Q - 1);
    const float* __restrict__ rowp = pred + (size_t)qc * P;

    const int pstart = k * pc;
    const int pend   = (pstart + pc < P) ? (pstart + pc) : P;

    // packed constants (loop-invariant)
    const uint64_t ONE = pk(1.0f, 1.0f);
    const uint64_t MONE= pk(-1.0f, -1.0f);
    const uint64_t TWO = pk(2.0f, 2.0f);
    const uint64_t CA  = pk(-0.470588235f, -0.470588235f);  // -8/17
    const uint64_t CB  = pk(1.411764706f, 1.411764706f);    // 24/17
    const uint64_t M3  = pk(-3.0f, -3.0f);
    const uint64_t A1  = pk(0.9999964239f, 0.9999964239f);
    const uint64_t A2  = pk(-0.4998741238f, -0.4998741238f);
    const uint64_t A3  = pk(0.3317990258f, 0.3317990258f);
    const uint64_t A4  = pk(-0.2407338084f, -0.2407338084f);
    const uint64_t A5  = pk(0.1676540711f, 0.1676540711f);
    const uint64_t A6  = pk(-0.0953293897f, -0.0953293897f);
    const uint64_t A7  = pk(0.0360884937f, 0.0360884937f);
    const uint64_t A8  = pk(-0.0064535442f, -0.0064535442f);

    uint64_t sumU2 = pk(0.f, 0.f);
    uint64_t sumV2 = pk(0.f, 0.f);

    const uint32_t accaddr = (uint32_t)__cvta_generic_to_shared(myacc);

    if (pstart < pend) {
        const int npts  = pend - pstart;
        const int nfull = npts >> 4;
        const int ntail = npts & 15;

        float4 b0, b1, b2, b3;
        uint4  lw;
        {
            const float* rp = rowp + pstart;
            b0 = *reinterpret_cast<const float4*>(rp + 0);
            b1 = *reinterpret_cast<const float4*>(rp + 4);
            b2 = *reinterpret_cast<const float4*>(rp + 8);
            b3 = *reinterpret_cast<const float4*>(rp + 12);
            lw = *reinterpret_cast<const uint4*>(g_labpack + (pstart >> 2));
        }

        int pt0 = pstart;
        for (int tile = 0; tile < nfull; ++tile, pt0 += TP) {
            float c[TP];
            c[0]=b0.x; c[1]=b0.y; c[2]=b0.z; c[3]=b0.w;
            c[4]=b1.x; c[5]=b1.y; c[6]=b1.z; c[7]=b1.w;
            c[8]=b2.x; c[9]=b2.y; c[10]=b2.z; c[11]=b2.w;
            c[12]=b3.x; c[13]=b3.y; c[14]=b3.z; c[15]=b3.w;
            uint32_t lv[4] = {lw.x, lw.y, lw.z, lw.w};

            const int nxt = pt0 + TP;
            if (nxt + TP <= pend) {
                const float* rp = rowp + nxt;
                b0 = *reinterpret_cast<const float4*>(rp + 0);
                b1 = *reinterpret_cast<const float4*>(rp + 4);
                b2 = *reinterpret_cast<const float4*>(rp + 8);
                b3 = *reinterpret_cast<const float4*>(rp + 12);
                lw = *reinterpret_cast<const uint4*>(g_labpack + (nxt >> 2));
            }

            #pragma unroll
            for (int i = 0; i < TP / 2; ++i) {
                const float x0 = c[2*i], x1 = c[2*i+1];
                const float ax0 = fabsf(x0), ax1 = fabsf(x1);
                const float t0 = __expf(-ax0);
                const float t1 = __expf(-ax1);

                const uint64_t t  = pk(t0, t1);
                const uint64_t m  = pk(ax0, ax1);
                const uint64_t dn = f2add(t, ONE);
                const uint64_t ndn= f2mul(dn, MONE);
                uint64_t r = f2fma(dn, CA, CB);          // Newton recip
                r = f2mul(r, f2fma(ndn, r, TWO));
                r = f2mul(r, f2fma(ndn, r, TWO));
                const uint64_t tr = f2mul(t, r);
                uint64_t pl = f2fma(t, A8, A7);          // Hastings log(1+t)
                pl = f2fma(t, pl, A6);
                pl = f2fma(t, pl, A5);
                pl = f2fma(t, pl, A4);
                pl = f2fma(t, pl, A3);
                pl = f2fma(t, pl, A2);
                pl = f2fma(t, pl, A1);
                const uint64_t L  = f2mul(pl, t);
                const uint64_t Lm = f2add(L, m);
                const uint64_t U  = f2mul(f2mul(tr, tr), L);
                const uint64_t V  = f2mul(f2mul(r, r), Lm);
                const uint64_t dU = f2fma(V, M3, U);     // U - 3V  (x>=0)
                const uint64_t dV = f2fma(U, M3, V);     // V - 3U  (x<0)

                sumU2 = f2add(sumU2, U);
                sumV2 = f2add(sumV2, V);

                float r_0, r_1, tr_0, tr_1, dU_0, dU_1, dV_0, dV_1;
                upk(r, r_0, r_1); upk(tr, tr_0, tr_1);
                upk(dU, dU_0, dU_1); upk(dV, dV_0, dV_1);

                {   // point 2i
                    const int lab = (int)__byte_perm(lv[i >> 1], 0,
                                                     0x4440u + ((2*i) & 3));
                    const bool pos = (x0 >= 0.0f);
                    const uint64_t ds = pk(pos ? dU_0 : dV_0, pos ? r_0 : tr_0);
                    const uint32_t ad = accaddr + (uint32_t)lab * 8u;
                    uint64_t a;
                    asm("ld.shared.b64 %0, [%1];" : "=l"(a) : "r"(ad));
                    a = f2add(a, ds);
                    asm("st.shared.b64 [%0], %1;" :: "r"(ad), "l"(a));
                }
                {   // point 2i+1
                    const int lab = (int)__byte_perm(lv[i >> 1], 0,
                                                     0x4440u + ((2*i+1) & 3));
                    const bool pos = (x1 >= 0.0f);
                    const uint64_t ds = pk(pos ? dU_1 : dV_1, pos ? r_1 : tr_1);
                    const uint32_t ad = accaddr + (uint32_t)lab * 8u;
                    uint64_t a;
                    asm("ld.shared.b64 %0, [%1];" : "=l"(a) : "r"(ad));
                    a = f2add(a, ds);
                    asm("st.shared.b64 [%0], %1;" :: "r"(ad), "l"(a));
                }
            }
        }

        if (ntail) {
            #pragma unroll
            for (int i = 0; i < TP; ++i) {
                if (i < ntail) {
                    const int lab = labels[pt0 + i];
                    float d, U, V, s;
                    point_math_scalar(rowp[pt0 + i], d, U, V, s);
                    float2 a = myacc[lab];
                    a.x += d; a.y += s;
                    myacc[lab] = a;
                    sumU2 = f2add(sumU2, pk(U, 0.f));
                    sumV2 = f2add(sumV2, pk(V, 0.f));
                }
            }
        }
    }

    float2* dst = g_acc + (size_t)g * NM * 32;
    #pragma unroll 4
    for (int j = 0; j < NM; ++j) dst[j * 32 + lane] = myacc[j];
    float su0, su1, sv0, sv1;
    upk(sumU2, su0, su1); upk(sumV2, sv0, sv1);
    g_sc[(size_t)g * 32 + lane] = make_float2(su0 + su1, sv0 + sv1);
}

// stage 1: grid (NM/8, WR, NSEG), block (32,8)
__global__ void reduce1_kernel() {
    const int lane = threadIdx.x;
    const int ty   = threadIdx.y;
    const int j    = blockIdx.x * 8 + ty;
    const int wr   = blockIdx.y;
    const int seg  = blockIdx.z;

    if (j < NM) {
        float s1 = 0.f, s2 = 0.f;
        const size_t base = (size_t)wr * KCH + seg * KSEG;
        #pragma unroll
        for (int k = 0; k < KSEG; ++k) {
            float2 a = g_acc[((base + k) * NM + j) * 32 + lane];
            s1 += a.x; s2 += a.y;
        }
        g_part[(((size_t)seg * NM + j) * WR + wr) * 32 + lane] = make_float2(s1, s2);
    }

    if (ty == 0 && blockIdx.x == 0) {
        float su = 0.f, sv = 0.f;
        const size_t base = (size_t)wr * KCH + seg * KSEG;
        #pragma unroll
        for (int k = 0; k < KSEG; ++k) {
            float2 s = g_sc[(base + k) * 32 + lane];
            su += s.x; sv += s.y;
        }
        g_spart[((size_t)seg * WR + wr) * 32 + lane] = make_float2(su, sv);
    }

    if (seg == 0 && wr == 0 && j < NM) {
        int c = 0;
        for (int b = lane; b < HBLK; b += 32) c += g_hist[b * NM + j];
        #pragma unroll
        for (int o = 16; o > 0; o >>= 1) c += __shfl_xor_sync(0xffffffffu, c, o);
        if (lane == 0) g_counts[j] = c;
    }
}

// per-query totals: Sd = sum_j bins.x, Sp = sum_j bins.y
__global__ void rowsum_kernel() {
    __shared__ float2 sb[8][33];
    const int lane = threadIdx.x;
    const int ty   = threadIdx.y;
    const int wr   = blockIdx.x;
    float sd = 0.f, sp = 0.f;
    for (int mm = 0; mm < 13; ++mm) {
        const int j = ty + 8 * mm;
        if (j < NM) {
            #pragma unroll
            for (int seg = 0; seg < NSEG; ++seg) {
                float2 a = g_part[(((size_t)seg * NM + j) * WR + wr) * 32 + lane];
                sd += a.x; sp += a.y;
            }
        }
    }
    sb[ty][lane] = make_float2(sd, sp);
    __syncthreads();
    if (ty == 0) {
        float2 tt = sb[0][lane];
        #pragma unroll
        for (int y = 1; y < 8; ++y) { tt.x += sb[y][lane].x; tt.y += sb[y][lane].y; }
        g_rowsum[wr * 32 + lane] = tt;
    }
}

// stage 2: grid (NM/8, WR), block (32,8)
__global__ void reduce2_kernel(float* __restrict__ out, int Q, float invP) {
    const int lane = threadIdx.x;
    const int j    = blockIdx.x * 8 + threadIdx.y;
    const int wr   = blockIdx.y;
    const int q    = wr * 32 + lane;
    if (q >= Q || j >= NM) return;

    float s1 = 0.f, s2 = 0.f, su = 0.f, sv = 0.f;
    #pragma unroll
    for (int seg = 0; seg < NSEG; ++seg) {
        float2 a = g_part[(((size_t)seg * NM + j) * WR + wr) * 32 + lane];
        float2 s = g_spart[((size_t)seg * WR + wr) * 32 + lane];
        s1 += a.x; s2 += a.y;
        su += s.x; sv += s.y;
    }
    const float2 rs = g_rowsum[wr * 32 + lane];   // (Sd, Sp)
    const float sumB = (su + sv - rs.x) * 0.25f;  // {A,B}={U,V}: B=(U+V-d)/4
    const float cnt = (float)g_counts[j];
    const float cost_mask = (0.25f * s1 + 0.75f * sumB) * invP;
    const float cost_dice = 1.0f - (2.0f * s2 + 1.0f) / (rs.y + cnt + 1.0f);
    out[(size_t)q * NM + j] = cost_mask + cost_dice;
}

extern "C" void kernel_launch(void* const* d_in, const int* in_sizes, int n_in,
                              void* d_out, int out_size) {
    const float* pred   = (const float*)d_in[0];
    const int*   labels = (const int*)d_in[1];

    const int P = in_sizes[1];
    const int Q = in_sizes[0] / P;
    const int pc = (((P + KCH - 1) / KCH) + TP - 1) / TP * TP;

    cudaFuncSetAttribute(main_kernel, cudaFuncAttributeMaxDynamicSharedMemorySize,
                         ACC_BYTES);

    pack_labels_kernel<<<(P / 4 + 256) / 256 + 1, 256>>>(labels, P);
    hist_kernel<<<HBLK, 256>>>(labels, P);
    main_kernel<<<148, BLK, ACC_BYTES>>>(pred, labels, Q, P, pc);
    reduce1_kernel<<<dim3((NM + 7) / 8, WR, NSEG), dim3(32, 8)>>>();
    rowsum_kernel<<<WR, dim3(32, 8)>>>();
    reduce2_kernel<<<dim3((NM + 7) / 8, WR), dim3(32, 8)>>>((float*)d_out, Q,
                                                            1.0f / (float)P);
}

// round 14
// speedup vs baseline: 1.0076x; 1.0032x over previous
#include <cuda_runtime.h>
#include <cstdint>

#define NM    100
#define NPAD  101          // padded bins per lane (odd stride -> conflict-free LDS.64)
#define WARPS 8
#define BLK   (WARPS*32)
#define TP    16
#define KCH   91           // 13 wr * 91 = 1183 tasks = 148*8-1 warps
#define WR    13
#define NTASK (WR*KCH)
#define NSEG  7
#define KSEG  13
#define HBLK  148

#define ACC_BYTES (BLK*NPAD*sizeof(float2))   /* 206848 B -> 1 block/SM, 8 warps */

__device__ float2   g_acc[(size_t)NTASK * NM * 32];   // ~30.3 MB
__device__ float2   g_sc [(size_t)NTASK * 32];        // (SumU, SumV) per task-lane
__device__ int      g_hist[HBLK * NM];
__device__ int      g_counts[NM];
__device__ uint32_t g_labpack[65536];
__device__ float2   g_part [(size_t)NSEG * NM * WR * 32];
__device__ float2   g_spart[(size_t)NSEG * WR * 32];
__device__ float2   g_rowsum[WR * 32];                // (Sum_d, Sum_s) per query

// ---------- packed f32x2 helpers ----------
__device__ __forceinline__ uint64_t pk(float lo, float hi) {
    uint64_t r; asm("mov.b64 %0, {%1,%2};" : "=l"(r) : "f"(lo), "f"(hi)); return r;
}
__device__ __forceinline__ void upk(uint64_t v, float& lo, float& hi) {
    asm("mov.b64 {%0,%1}, %2;" : "=f"(lo), "=f"(hi) : "l"(v));
}
__device__ __forceinline__ uint64_t f2add(uint64_t a, uint64_t b) {
    uint64_t d; asm("add.rn.f32x2 %0, %1, %2;" : "=l"(d) : "l"(a), "l"(b)); return d;
}
__device__ __forceinline__ uint64_t f2mul(uint64_t a, uint64_t b) {
    uint64_t d; asm("mul.rn.f32x2 %0, %1, %2;" : "=l"(d) : "l"(a), "l"(b)); return d;
}
__device__ __forceinline__ uint64_t f2fma(uint64_t a, uint64_t b, uint64_t c) {
    uint64_t d; asm("fma.rn.f32x2 %0, %1, %2, %3;" : "=l"(d) : "l"(a), "l"(b), "l"(c)); return d;
}

__global__ void pack_labels_kernel(const int* __restrict__ labels, int P) {
    const int i = blockIdx.x * blockDim.x + threadIdx.x;
    const int base = i * 4;
    if (base >= P) return;
    uint32_t w = 0;
    if (base + 3 < P) {
        int4 l = *reinterpret_cast<const int4*>(labels + base);
        w = (uint32_t)(l.x & 0xFF) | ((uint32_t)(l.y & 0xFF) << 8) |
            ((uint32_t)(l.z & 0xFF) << 16) | ((uint32_t)(l.w & 0xFF) << 24);
    } else {
        for (int k = 0; k < 4 && base + k < P; ++k)
            w |= (uint32_t)(labels[base + k] & 0xFF) << (8 * k);
    }
    g_labpack[i] = w;
}

__global__ void hist_kernel(const int* __restrict__ labels, int P) {
    __shared__ int sb[NM];
    for (int i = threadIdx.x; i < NM; i += blockDim.x) sb[i] = 0;
    __syncthreads();
    for (int i = blockIdx.x * blockDim.x + threadIdx.x; i < P;
         i += gridDim.x * blockDim.x) {
        int l = labels[i];
        if ((unsigned)l < (unsigned)NM) atomicAdd(&sb[l], 1);
    }
    __syncthreads();
    for (int i = threadIdx.x; i < NM; i += blockDim.x)
        g_hist[blockIdx.x * NM + i] = sb[i];
}

// scalar fallback for tail points (uses MUFU log; rarely executed)
__device__ __forceinline__ void point_math_scalar(float x, float& d, float& U,
                                                  float& V, float& s) {
    const float ax = fabsf(x);
    const float t  = __expf(-ax);
    const float dn = 1.0f + t;
    const float r  = __fdividef(1.0f, dn);
    const float tr = t * r;
    const float L  = __logf(dn);
    const float Lm = L + ax;
    U = (tr * tr) * L;
    V = (r * r) * Lm;
    const bool pos = (x >= 0.0f);
    s = pos ? r : tr;
    d = pos ? fmaf(-3.0f, V, U) : fmaf(-3.0f, U, V);
}

__global__ __launch_bounds__(BLK, 1)
void main_kernel(const float* __restrict__ pred, const int* __restrict__ labels,
                 int Q, int P, int pc) {
    extern __shared__ float2 acc[];

    const int tid  = threadIdx.x;
    const int w    = tid >> 5;
    const int lane = tid & 31;

    float2* myacc = acc + tid * NPAD;
    #pragma unroll 4
    for (int j = 0; j < NPAD; ++j) myacc[j] = make_float2(0.f, 0.f);

    const int g = w * gridDim.x + blockIdx.x;
    if (g >= NTASK) return;
    const int wr = g / KCH;
    const int k  = g - wr * KCH;

    const int q  = wr * 32 + lane;
    const int qc = (q < Q) ? q : (Q - 1);
    const float* __restrict__ rowp = pred + (size_t)qc * P;

    const int pstart = k * pc;
    const int pend   = (pstart + pc < P) ? (pstart + pc) : P;

    // packed constants (loop-invariant)
    const uint64_t ONE = pk(1.0f, 1.0f);
    const uint64_t MONE= pk(-1.0f, -1.0f);
    const uint64_t TWO = pk(2.0f, 2.0f);
    const uint64_t CA  = pk(-0.470588235f, -0.470588235f);  // -8/17
    const uint64_t CB  = pk(1.411764706f, 1.411764706f);    // 24/17
    const uint64_t M3  = pk(-3.0f, -3.0f);
    const uint64_t A1  = pk(0.9999964239f, 0.9999964239f);
    const uint64_t A2  = pk(-0.4998741238f, -0.4998741238f);
    const uint64_t A3  = pk(0.3317990258f, 0.3317990258f);
    const uint64_t A4  = pk(-0.2407338084f, -0.2407338084f);
    const uint64_t A5  = pk(0.1676540711f, 0.1676540711f);
    const uint64_t A6  = pk(-0.0953293897f, -0.0953293897f);
    const uint64_t A7  = pk(0.0360884937f, 0.0360884937f);
    const uint64_t A8  = pk(-0.0064535442f, -0.0064535442f);

    uint64_t sumU2 = pk(0.f, 0.f);
    uint64_t sumV2 = pk(0.f, 0.f);

    const uint32_t accaddr = (uint32_t)__cvta_generic_to_shared(myacc);

    if (pstart < pend) {
        const int npts  = pend - pstart;
        const int nfull = npts >> 4;
        const int ntail = npts & 15;

        float4 b0, b1, b2, b3;
        uint4  lw;
        {
            const float* rp = rowp + pstart;
            b0 = *reinterpret_cast<const float4*>(rp + 0);
            b1 = *reinterpret_cast<const float4*>(rp + 4);
            b2 = *reinterpret_cast<const float4*>(rp + 8);
            b3 = *reinterpret_cast<const float4*>(rp + 12);
            lw = *reinterpret_cast<const uint4*>(g_labpack + (pstart >> 2));
        }

        int pt0 = pstart;
        for (int tile = 0; tile < nfull; ++tile, pt0 += TP) {
            float c[TP];
            c[0]=b0.x; c[1]=b0.y; c[2]=b0.z; c[3]=b0.w;
            c[4]=b1.x; c[5]=b1.y; c[6]=b1.z; c[7]=b1.w;
            c[8]=b2.x; c[9]=b2.y; c[10]=b2.z; c[11]=b2.w;
            c[12]=b3.x; c[13]=b3.y; c[14]=b3.z; c[15]=b3.w;
            uint32_t lv[4] = {lw.x, lw.y, lw.z, lw.w};

            const int nxt = pt0 + TP;
            if (nxt + TP <= pend) {
                const float* rp = rowp + nxt;
                b0 = *reinterpret_cast<const float4*>(rp + 0);
                b1 = *reinterpret_cast<const float4*>(rp + 4);
                b2 = *reinterpret_cast<const float4*>(rp + 8);
                b3 = *reinterpret_cast<const float4*>(rp + 12);
                lw = *reinterpret_cast<const uint4*>(g_labpack + (nxt >> 2));
            }

            #pragma unroll
            for (int i = 0; i < TP / 2; ++i) {
                const float x0 = c[2*i], x1 = c[2*i+1];
                const float ax0 = fabsf(x0), ax1 = fabsf(x1);
                const float t0 = __expf(-ax0);
                const float t1 = __expf(-ax1);

                const uint64_t t  = pk(t0, t1);
                const uint64_t m  = pk(ax0, ax1);
                const uint64_t dn = f2add(t, ONE);
                const uint64_t ndn= f2mul(dn, MONE);
                uint64_t r = f2fma(dn, CA, CB);          // Newton recip
                r = f2mul(r, f2fma(ndn, r, TWO));
                r = f2mul(r, f2fma(ndn, r, TWO));
                const uint64_t tr = f2mul(t, r);
                uint64_t pl = f2fma(t, A8, A7);          // Hastings log(1+t)
                pl = f2fma(t, pl, A6);
                pl = f2fma(t, pl, A5);
                pl = f2fma(t, pl, A4);
                pl = f2fma(t, pl, A3);
                pl = f2fma(t, pl, A2);
                pl = f2fma(t, pl, A1);
                const uint64_t L  = f2mul(pl, t);
                const uint64_t Lm = f2add(L, m);
                const uint64_t U  = f2mul(f2mul(tr, tr), L);
                const uint64_t V  = f2mul(f2mul(r, r), Lm);
                const uint64_t dU = f2fma(V, M3, U);     // U - 3V  (x>=0)
                const uint64_t dV = f2fma(U, M3, V);     // V - 3U  (x<0)

                sumU2 = f2add(sumU2, U);
                sumV2 = f2add(sumV2, V);

                float r_0, r_1, tr_0, tr_1, dU_0, dU_1, dV_0, dV_1;
                upk(r, r_0, r_1); upk(tr, tr_0, tr_1);
                upk(dU, dU_0, dU_1); upk(dV, dV_0, dV_1);

                {   // point 2i
                    const int lab = (int)__byte_perm(lv[i >> 1], 0,
                                                     0x4440u + ((2*i) & 3));
                    const bool pos = (x0 >= 0.0f);
                    const uint64_t ds = pk(pos ? dU_0 : dV_0, pos ? r_0 : tr_0);
                    const uint32_t ad = accaddr + (uint32_t)lab * 8u;
                    uint64_t a;
                    asm("ld.shared.b64 %0, [%1];" : "=l"(a) : "r"(ad));
                    a = f2add(a, ds);
                    asm("st.shared.b64 [%0], %1;" :: "r"(ad), "l"(a));
                }
                {   // point 2i+1
                    const int lab = (int)__byte_perm(lv[i >> 1], 0,
                                                     0x4440u + ((2*i+1) & 3));
                    const bool pos = (x1 >= 0.0f);
                    const uint64_t ds = pk(pos ? dU_1 : dV_1, pos ? r_1 : tr_1);
                    const uint32_t ad = accaddr + (uint32_t)lab * 8u;
                    uint64_t a;
                    asm("ld.shared.b64 %0, [%1];" : "=l"(a) : "r"(ad));
                    a = f2add(a, ds);
                    asm("st.shared.b64 [%0], %1;" :: "r"(ad), "l"(a));
                }
            }
        }

        if (ntail) {
            #pragma unroll
            for (int i = 0; i < TP; ++i) {
                if (i < ntail) {
                    const int lab = labels[pt0 + i];
                    float d, U, V, s;
                    point_math_scalar(rowp[pt0 + i], d, U, V, s);
                    float2 a = myacc[lab];
                    a.x += d; a.y += s;
                    myacc[lab] = a;
                    sumU2 = f2add(sumU2, pk(U, 0.f));
                    sumV2 = f2add(sumV2, pk(V, 0.f));
                }
            }
        }
    }

    float2* dst = g_acc + (size_t)g * NM * 32;
    #pragma unroll 4
    for (int j = 0; j < NM; ++j) dst[j * 32 + lane] = myacc[j];
    float su0, su1, sv0, sv1;
    upk(sumU2, su0, su1); upk(sumV2, sv0, sv1);
    g_sc[(size_t)g * 32 + lane] = make_float2(su0 + su1, sv0 + sv1);
}

// stage 1: grid (NM/8, WR, NSEG), block (32,8)
__global__ void reduce1_kernel() {
    const int lane = threadIdx.x;
    const int ty   = threadIdx.y;
    const int j    = blockIdx.x * 8 + ty;
    const int wr   = blockIdx.y;
    const int seg  = blockIdx.z;

    if (j < NM) {
        float s1 = 0.f, s2 = 0.f;
        const size_t base = (size_t)wr * KCH + seg * KSEG;
        #pragma unroll
        for (int k = 0; k < KSEG; ++k) {
            float2 a = g_acc[((base + k) * NM + j) * 32 + lane];
            s1 += a.x; s2 += a.y;
        }
        g_part[(((size_t)seg * NM + j) * WR + wr) * 32 + lane] = make_float2(s1, s2);
    }

    if (ty == 0 && blockIdx.x == 0) {
        float su = 0.f, sv = 0.f;
        const size_t base = (size_t)wr * KCH + seg * KSEG;
        #pragma unroll
        for (int k = 0; k < KSEG; ++k) {
            float2 s = g_sc[(base + k) * 32 + lane];
            su += s.x; sv += s.y;
        }
        g_spart[((size_t)seg * WR + wr) * 32 + lane] = make_float2(su, sv);
    }

    if (seg == 0 && wr == 0 && j < NM) {
        int c = 0;
        for (int b = lane; b < HBLK; b += 32) c += g_hist[b * NM + j];
        #pragma unroll
        for (int o = 16; o > 0; o >>= 1) c += __shfl_xor_sync(0xffffffffu, c, o);
        if (lane == 0) g_counts[j] = c;
    }
}

// per-query totals: Sd = sum_j bins.x, Sp = sum_j bins.y
__global__ void rowsum_kernel() {
    __shared__ float2 sb[8][33];
    const int lane = threadIdx.x;
    const int ty   = threadIdx.y;
    const int wr   = blockIdx.x;
    float sd = 0.f, sp = 0.f;
    for (int mm = 0; mm < 13; ++mm) {
        const int j = ty + 8 * mm;
        if (j < NM) {
            #pragma unroll
            for (int seg = 0; seg < NSEG; ++seg) {
                float2 a = g_part[(((size_t)seg * NM + j) * WR + wr) * 32 + lane];
                sd += a.x; sp += a.y;
            }
        }
    }
    sb[ty][lane] = make_float2(sd, sp);
    __syncthreads();
    if (ty == 0) {
        float2 tt = sb[0][lane];
        #pragma unroll
        for (int y = 1; y < 8; ++y) { tt.x += sb[y][lane].x; tt.y += sb[y][lane].y; }
        g_rowsum[wr * 32 + lane] = tt;
    }
}

// stage 2: grid (NM/8, WR), block (32,8)
__global__ void reduce2_kernel(float* __restrict__ out, int Q, float invP) {
    const int lane = threadIdx.x;
    const int j    = blockIdx.x * 8 + threadIdx.y;
    const int wr   = blockIdx.y;
    const int q    = wr * 32 + lane;
    if (q >= Q || j >= NM) return;

    float s1 = 0.f, s2 = 0.f, su = 0.f, sv = 0.f;
    #pragma unroll
    for (int seg = 0; seg < NSEG; ++seg) {
        float2 a = g_part[(((size_t)seg * NM + j) * WR + wr) * 32 + lane];
        float2 s = g_spart[((size_t)seg * WR + wr) * 32 + lane];
        s1 += a.x; s2 += a.y;
        su += s.x; sv += s.y;
    }
    const float2 rs = g_rowsum[wr * 32 + lane];   // (Sd, Sp)
    const float sumB = (su + sv - rs.x) * 0.25f;  // {A,B}={U,V}: B=(U+V-d)/4
    const float cnt = (float)g_counts[j];
    const float cost_mask = (0.25f * s1 + 0.75f * sumB) * invP;
    const float cost_dice = 1.0f - (2.0f * s2 + 1.0f) / (rs.y + cnt + 1.0f);
    out[(size_t)q * NM + j] = cost_mask + cost_dice;
}

extern "C" void kernel_launch(void* const* d_in, const int* in_sizes, int n_in,
                              void* d_out, int out_size) {
    const float* pred   = (const float*)d_in[0];
    const int*   labels = (const int*)d_in[1];

    const int P = in_sizes[1];
    const int Q = in_sizes[0] / P;
    const int pc = (((P + KCH - 1) / KCH) + TP - 1) / TP * TP;

    cudaFuncSetAttribute(main_kernel, cudaFuncAttributeMaxDynamicSharedMemorySize,
                         ACC_BYTES);

    pack_labels_kernel<<<(P / 4 + 256) / 256 + 1, 256>>>(labels, P);
    hist_kernel<<<HBLK, 256>>>(labels, P);
    main_kernel<<<148, BLK, ACC_BYTES>>>(pred, labels, Q, P, pc);
    reduce1_kernel<<<dim3((NM + 7) / 8, WR, NSEG), dim3(32, 8)>>>();
    rowsum_kernel<<<WR, dim3(32, 8)>>>();
    reduce2_kernel<<<dim3((NM + 7) / 8, WR), dim3(32, 8)>>>((float*)d_out, Q,
                                                            1.0f / (float)P);
}

// round 15
// speedup vs baseline: 1.0106x; 1.0030x over previous
#include <cuda_runtime.h>
#include <cstdint>

#define NM    100
#define NPAD  101          // padded bins per lane (odd stride -> conflict-free LDS.64)
#define WARPS 8
#define BLK   (WARPS*32)
#define TP    16
#define KCH   91           // 13 wr * 91 = 1183 tasks = 148*8-1 warps
#define WR    13
#define NTASK (WR*KCH)
#define NSEG  7
#define KSEG  13
#define HBLK  148

#define ACC_BYTES (BLK*NPAD*sizeof(float2))   /* 206848 B -> 1 block/SM, 8 warps */

__device__ float2   g_acc[(size_t)NTASK * NM * 32];   // ~30.3 MB
__device__ float2   g_sc [(size_t)NTASK * 32];        // (SumU, SumV) per task-lane
__device__ int      g_hist[HBLK * NM];
__device__ int      g_counts[NM];
__device__ uint32_t g_labpack[65536];
__device__ float2   g_part [(size_t)NSEG * NM * WR * 32];
__device__ float2   g_spart[(size_t)NSEG * WR * 32];
__device__ float2   g_rowsum[WR * 32];                // (Sum_d, Sum_s) per query

// ---------- packed f32x2 helpers ----------
__device__ __forceinline__ uint64_t pk(float lo, float hi) {
    uint64_t r; asm("mov.b64 %0, {%1,%2};" : "=l"(r) : "f"(lo), "f"(hi)); return r;
}
__device__ __forceinline__ void upk(uint64_t v, float& lo, float& hi) {
    asm("mov.b64 {%0,%1}, %2;" : "=f"(lo), "=f"(hi) : "l"(v));
}
__device__ __forceinline__ uint64_t f2add(uint64_t a, uint64_t b) {
    uint64_t d; asm("add.rn.f32x2 %0, %1, %2;" : "=l"(d) : "l"(a), "l"(b)); return d;
}
__device__ __forceinline__ uint64_t f2mul(uint64_t a, uint64_t b) {
    uint64_t d; asm("mul.rn.f32x2 %0, %1, %2;" : "=l"(d) : "l"(a), "l"(b)); return d;
}
__device__ __forceinline__ uint64_t f2fma(uint64_t a, uint64_t b, uint64_t c) {
    uint64_t d; asm("fma.rn.f32x2 %0, %1, %2, %3;" : "=l"(d) : "l"(a), "l"(b), "l"(c)); return d;
}

__global__ void pack_labels_kernel(const int* __restrict__ labels, int P) {
    const int i = blockIdx.x * blockDim.x + threadIdx.x;
    const int base = i * 4;
    if (base >= P) return;
    uint32_t w = 0;
    if (base + 3 < P) {
        int4 l = *reinterpret_cast<const int4*>(labels + base);
        w = (uint32_t)(l.x & 0xFF) | ((uint32_t)(l.y & 0xFF) << 8) |
            ((uint32_t)(l.z & 0xFF) << 16) | ((uint32_t)(l.w & 0xFF) << 24);
    } else {
        for (int k = 0; k < 4 && base + k < P; ++k)
            w |= (uint32_t)(labels[base + k] & 0xFF) << (8 * k);
    }
    g_labpack[i] = w;
}

__global__ void hist_kernel(const int* __restrict__ labels, int P) {
    __shared__ int sb[NM];
    for (int i = threadIdx.x; i < NM; i += blockDim.x) sb[i] = 0;
    __syncthreads();
    for (int i = blockIdx.x * blockDim.x + threadIdx.x; i < P;
         i += gridDim.x * blockDim.x) {
        int l = labels[i];
        if ((unsigned)l < (unsigned)NM) atomicAdd(&sb[l], 1);
    }
    __syncthreads();
    for (int i = threadIdx.x; i < NM; i += blockDim.x)
        g_hist[blockIdx.x * NM + i] = sb[i];
}

// scalar fallback for tail points (uses MUFU log; rarely executed)
__device__ __forceinline__ void point_math_scalar(float x, float& d, float& U,
                                                  float& V, float& s) {
    const float ax = fabsf(x);
    const float t  = __expf(-ax);
    const float dn = 1.0f + t;
    const float r  = __fdividef(1.0f, dn);
    const float tr = t * r;
    const float L  = __logf(dn);
    const float Lm = L + ax;
    U = (tr * tr) * L;
    V = (r * r) * Lm;
    const bool pos = (x >= 0.0f);
    s = pos ? r : tr;
    d = pos ? fmaf(-3.0f, V, U) : fmaf(-3.0f, U, V);
}

__global__ __launch_bounds__(BLK, 1)
void main_kernel(const float* __restrict__ pred, const int* __restrict__ labels,
                 int Q, int P, int pc) {
    extern __shared__ float2 acc[];

    const int tid  = threadIdx.x;
    const int w    = tid >> 5;
    const int lane = tid & 31;

    float2* myacc = acc + tid * NPAD;
    #pragma unroll 4
    for (int j = 0; j < NPAD; ++j) myacc[j] = make_float2(0.f, 0.f);

    const int g = w * gridDim.x + blockIdx.x;
    if (g >= NTASK) return;
    const int wr = g / KCH;
    const int k  = g - wr * KCH;

    const int q  = wr * 32 + lane;
    const int qc = (q < Q) ? q : (Q - 1);
    const float* __restrict__ rowp = pred + (size_t)qc * P;

    const int pstart = k * pc;
    const int pend   = (pstart + pc < P) ? (pstart + pc) : P;

    // packed constants (loop-invariant)
    const uint64_t ONE = pk(1.0f, 1.0f);
    const uint64_t MONE= pk(-1.0f, -1.0f);
    const uint64_t TWO = pk(2.0f, 2.0f);
    const uint64_t CA  = pk(-0.470588235f, -0.470588235f);  // -8/17
    const uint64_t CB  = pk(1.411764706f, 1.411764706f);    // 24/17
    const uint64_t M3  = pk(-3.0f, -3.0f);
    const uint64_t A1  = pk(0.9999964239f, 0.9999964239f);
    const uint64_t A2  = pk(-0.4998741238f, -0.4998741238f);
    const uint64_t A3  = pk(0.3317990258f, 0.3317990258f);
    const uint64_t A4  = pk(-0.2407338084f, -0.2407338084f);
    const uint64_t A5  = pk(0.1676540711f, 0.1676540711f);
    const uint64_t A6  = pk(-0.0953293897f, -0.0953293897f);
    const uint64_t A7  = pk(0.0360884937f, 0.0360884937f);
    const uint64_t A8  = pk(-0.0064535442f, -0.0064535442f);

    uint64_t sumU2 = pk(0.f, 0.f);
    uint64_t sumV2 = pk(0.f, 0.f);

    const uint32_t accaddr = (uint32_t)__cvta_generic_to_shared(myacc);

    if (pstart < pend) {
        const int npts  = pend - pstart;
        const int nfull = npts >> 4;
        const int ntail = npts & 15;

        float4 b0, b1, b2, b3;
        uint4  lw;
        {
            const float* rp = rowp + pstart;
            b0 = *reinterpret_cast<const float4*>(rp + 0);
            b1 = *reinterpret_cast<const float4*>(rp + 4);
            b2 = *reinterpret_cast<const float4*>(rp + 8);
            b3 = *reinterpret_cast<const float4*>(rp + 12);
            lw = *reinterpret_cast<const uint4*>(g_labpack + (pstart >> 2));
        }

        int pt0 = pstart;
        for (int tile = 0; tile < nfull; ++tile, pt0 += TP) {
            float c[TP];
            c[0]=b0.x; c[1]=b0.y; c[2]=b0.z; c[3]=b0.w;
            c[4]=b1.x; c[5]=b1.y; c[6]=b1.z; c[7]=b1.w;
            c[8]=b2.x; c[9]=b2.y; c[10]=b2.z; c[11]=b2.w;
            c[12]=b3.x; c[13]=b3.y; c[14]=b3.z; c[15]=b3.w;
            uint32_t lv[4] = {lw.x, lw.y, lw.z, lw.w};

            const int nxt = pt0 + TP;
            if (nxt + TP <= pend) {
                const float* rp = rowp + nxt;
                b0 = *reinterpret_cast<const float4*>(rp + 0);
                b1 = *reinterpret_cast<const float4*>(rp + 4);
                b2 = *reinterpret_cast<const float4*>(rp + 8);
                b3 = *reinterpret_cast<const float4*>(rp + 12);
                lw = *reinterpret_cast<const uint4*>(g_labpack + (nxt >> 2));
            }

            #pragma unroll
            for (int i = 0; i < TP / 2; ++i) {
                const float x0 = c[2*i], x1 = c[2*i+1];
                const float ax0 = fabsf(x0), ax1 = fabsf(x1);
                const float t0 = __expf(-ax0);
                const float t1 = __expf(-ax1);

                const uint64_t t  = pk(t0, t1);
                const uint64_t m  = pk(ax0, ax1);
                const uint64_t dn = f2add(t, ONE);
                const uint64_t ndn= f2mul(dn, MONE);
                uint64_t r = f2fma(dn, CA, CB);          // Newton recip
                r = f2mul(r, f2fma(ndn, r, TWO));
                r = f2mul(r, f2fma(ndn, r, TWO));
                const uint64_t tr = f2mul(t, r);
                uint64_t pl = f2fma(t, A8, A7);          // Hastings log(1+t)
                pl = f2fma(t, pl, A6);
                pl = f2fma(t, pl, A5);
                pl = f2fma(t, pl, A4);
                pl = f2fma(t, pl, A3);
                pl = f2fma(t, pl, A2);
                pl = f2fma(t, pl, A1);
                const uint64_t L  = f2mul(pl, t);
                const uint64_t Lm = f2add(L, m);
                const uint64_t U  = f2mul(f2mul(tr, tr), L);
                const uint64_t V  = f2mul(f2mul(r, r), Lm);
                const uint64_t dU = f2fma(V, M3, U);     // U - 3V  (x>=0)
                const uint64_t dV = f2fma(U, M3, V);     // V - 3U  (x<0)

                sumU2 = f2add(sumU2, U);
                sumV2 = f2add(sumV2, V);

                float r_0, r_1, tr_0, tr_1, dU_0, dU_1, dV_0, dV_1;
                upk(r, r_0, r_1); upk(tr, tr_0, tr_1);
                upk(dU, dU_0, dU_1); upk(dV, dV_0, dV_1);

                {   // point 2i
                    const int lab = (int)__byte_perm(lv[i >> 1], 0,
                                                     0x4440u + ((2*i) & 3));
                    const bool pos = (x0 >= 0.0f);
                    const uint64_t ds = pk(pos ? dU_0 : dV_0, pos ? r_0 : tr_0);
                    const uint32_t ad = accaddr + (uint32_t)lab * 8u;
                    uint64_t a;
                    asm("ld.shared.b64 %0, [%1];" : "=l"(a) : "r"(ad));
                    a = f2add(a, ds);
                    asm("st.shared.b64 [%0], %1;" :: "r"(ad), "l"(a));
                }
                {   // point 2i+1
                    const int lab = (int)__byte_perm(lv[i >> 1], 0,
                                                     0x4440u + ((2*i+1) & 3));
                    const bool pos = (x1 >= 0.0f);
                    const uint64_t ds = pk(pos ? dU_1 : dV_1, pos ? r_1 : tr_1);
                    const uint32_t ad = accaddr + (uint32_t)lab * 8u;
                    uint64_t a;
                    asm("ld.shared.b64 %0, [%1];" : "=l"(a) : "r"(ad));
                    a = f2add(a, ds);
                    asm("st.shared.b64 [%0], %1;" :: "r"(ad), "l"(a));
                }
            }
        }

        if (ntail) {
            #pragma unroll
            for (int i = 0; i < TP; ++i) {
                if (i < ntail) {
                    const int lab = labels[pt0 + i];
                    float d, U, V, s;
                    point_math_scalar(rowp[pt0 + i], d, U, V, s);
                    float2 a = myacc[lab];
                    a.x += d; a.y += s;
                    myacc[lab] = a;
                    sumU2 = f2add(sumU2, pk(U, 0.f));
                    sumV2 = f2add(sumV2, pk(V, 0.f));
                }
            }
        }
    }

    float2* dst = g_acc + (size_t)g * NM * 32;
    #pragma unroll 4
    for (int j = 0; j < NM; ++j) dst[j * 32 + lane] = myacc[j];
    float su0, su1, sv0, sv1;
    upk(sumU2, su0, su1); upk(sumV2, sv0, sv1);
    g_sc[(size_t)g * 32 + lane] = make_float2(su0 + su1, sv0 + sv1);
}

// stage 1: grid (NM/8, WR, NSEG), block (32,8)
__global__ void reduce1_kernel() {
    const int lane = threadIdx.x;
    const int ty   = threadIdx.y;
    const int j    = blockIdx.x * 8 + ty;
    const int wr   = blockIdx.y;
    const int seg  = blockIdx.z;

    if (j < NM) {
        float s1 = 0.f, s2 = 0.f;
        const size_t base = (size_t)wr * KCH + seg * KSEG;
        #pragma unroll
        for (int k = 0; k < KSEG; ++k) {
            float2 a = g_acc[((base + k) * NM + j) * 32 + lane];
            s1 += a.x; s2 += a.y;
        }
        g_part[(((size_t)seg * NM + j) * WR + wr) * 32 + lane] = make_float2(s1, s2);
    }

    if (ty == 0 && blockIdx.x == 0) {
        float su = 0.f, sv = 0.f;
        const size_t base = (size_t)wr * KCH + seg * KSEG;
        #pragma unroll
        for (int k = 0; k < KSEG; ++k) {
            float2 s = g_sc[(base + k) * 32 + lane];
            su += s.x; sv += s.y;
        }
        g_spart[((size_t)seg * WR + wr) * 32 + lane] = make_float2(su, sv);
    }

    if (seg == 0 && wr == 0 && j < NM) {
        int c = 0;
        for (int b = lane; b < HBLK; b += 32) c += g_hist[b * NM + j];
        #pragma unroll
        for (int o = 16; o > 0; o >>= 1) c += __shfl_xor_sync(0xffffffffu, c, o);
        if (lane == 0) g_counts[j] = c;
    }
}

// per-query totals: Sd = sum_j bins.x, Sp = sum_j bins.y
__global__ void rowsum_kernel() {
    __shared__ float2 sb[8][33];
    const int lane = threadIdx.x;
    const int ty   = threadIdx.y;
    const int wr   = blockIdx.x;
    float sd = 0.f, sp = 0.f;
    for (int mm = 0; mm < 13; ++mm) {
        const int j = ty + 8 * mm;
        if (j < NM) {
            #pragma unroll
            for (int seg = 0; seg < NSEG; ++seg) {
                float2 a = g_part[(((size_t)seg * NM + j) * WR + wr) * 32 + lane];
                sd += a.x; sp += a.y;
            }
        }
    }
    sb[ty][lane] = make_float2(sd, sp);
    __syncthreads();
    if (ty == 0) {
        float2 tt = sb[0][lane];
        #pragma unroll
        for (int y = 1; y < 8; ++y) { tt.x += sb[y][lane].x; tt.y += sb[y][lane].y; }
        g_rowsum[wr * 32 + lane] = tt;
    }
}

// stage 2: grid (NM/8, WR), block (32,8)
__global__ void reduce2_kernel(float* __restrict__ out, int Q, float invP) {
    const int lane = threadIdx.x;
    const int j    = blockIdx.x * 8 + threadIdx.y;
    const int wr   = blockIdx.y;
    const int q    = wr * 32 + lane;
    if (q >= Q || j >= NM) return;

    float s1 = 0.f, s2 = 0.f, su = 0.f, sv = 0.f;
    #pragma unroll
    for (int seg = 0; seg < NSEG; ++seg) {
        float2 a = g_part[(((size_t)seg * NM + j) * WR + wr) * 32 + lane];
        float2 s = g_spart[((size_t)seg * WR + wr) * 32 + lane];
        s1 += a.x; s2 += a.y;
        su += s.x; sv += s.y;
    }
    const float2 rs = g_rowsum[wr * 32 + lane];   // (Sd, Sp)
    const float sumB = (su + sv - rs.x) * 0.25f;  // {A,B}={U,V}: B=(U+V-d)/4
    const float cnt = (float)g_counts[j];
    const float cost_mask = (0.25f * s1 + 0.75f * sumB) * invP;
    const float cost_dice = 1.0f - (2.0f * s2 + 1.0f) / (rs.y + cnt + 1.0f);
    out[(size_t)q * NM + j] = cost_mask + cost_dice;
}

extern "C" void kernel_launch(void* const* d_in, const int* in_sizes, int n_in,
                              void* d_out, int out_size) {
    const float* pred   = (const float*)d_in[0];
    const int*   labels = (const int*)d_in[1];

    const int P = in_sizes[1];
    const int Q = in_sizes[0] / P;
    const int pc = (((P + KCH - 1) / KCH) + TP - 1) / TP * TP;

    cudaFuncSetAttribute(main_kernel, cudaFuncAttributeMaxDynamicSharedMemorySize,
                         ACC_BYTES);

    pack_labels_kernel<<<(P / 4 + 256) / 256 + 1, 256>>>(labels, P);
    hist_kernel<<<HBLK, 256>>>(labels, P);
    main_kernel<<<148, BLK, ACC_BYTES>>>(pred, labels, Q, P, pc);
    reduce1_kernel<<<dim3((NM + 7) / 8, WR, NSEG), dim3(32, 8)>>>();
    rowsum_kernel<<<WR, dim3(32, 8)>>>();
    reduce2_kernel<<<dim3((NM + 7) / 8, WR), dim3(32, 8)>>>((float*)d_out, Q,
                                                            1.0f / (float)P);
}